// round 3
// baseline (speedup 1.0000x reference)
#include <cuda_runtime.h>
#include <cuda_fp16.h>
#include <cstdint>

#define DIM 1024
#define M_TOTAL 8192
#define N_TOTAL 3072
#define RANK 16

// ---------------- scratch (module-static device arrays; no runtime alloc) ----
__device__ __half g_X16[(size_t)M_TOTAL * DIM];   // 16 MB fp16 activations
__device__ __half g_W16[(size_t)N_TOTAL * DIM];   // 6 MB fp16 merged weights

// ---------------- PTX helpers (baseline ISA only: sm_80-era) ------------------
__device__ __forceinline__ uint32_t smem_u32(const void* p) {
    uint32_t a;
    asm("{ .reg .u64 t; cvta.to.shared.u64 t, %1; cvt.u32.u64 %0, t; }" : "=r"(a) : "l"(p));
    return a;
}

#define CP_ASYNC16(dst_smem, src_g) \
    asm volatile("cp.async.cg.shared.global [%0], [%1], 16;" :: "r"(dst_smem), "l"(src_g) : "memory")
#define CP_ASYNC_COMMIT() asm volatile("cp.async.commit_group;" ::: "memory")
#define CP_ASYNC_WAIT(n)  asm volatile("cp.async.wait_group %0;" :: "n"(n) : "memory")

__device__ __forceinline__ void ldmatrix_x4(uint32_t* r, uint32_t addr) {
    asm volatile("ldmatrix.sync.aligned.m8n8.x4.shared.b16 {%0,%1,%2,%3}, [%4];"
                 : "=r"(r[0]), "=r"(r[1]), "=r"(r[2]), "=r"(r[3]) : "r"(addr));
}

__device__ __forceinline__ void mma16816(float* c, const uint32_t* a,
                                         uint32_t b0, uint32_t b1) {
    asm volatile(
        "mma.sync.aligned.m16n8k16.row.col.f32.f16.f16.f32 "
        "{%0,%1,%2,%3}, {%4,%5,%6,%7}, {%8,%9}, {%0,%1,%2,%3};"
        : "+f"(c[0]), "+f"(c[1]), "+f"(c[2]), "+f"(c[3])
        : "r"(a[0]), "r"(a[1]), "r"(a[2]), "r"(a[3]), "r"(b0), "r"(b1));
}

// ---------------- kernel 1: x fp32 -> fp16 ------------------------------------
__global__ void convert_x_kernel(const float* __restrict__ x) {
    size_t i = ((size_t)blockIdx.x * 256 + threadIdx.x) * 8;
    float4 a = *reinterpret_cast<const float4*>(x + i);
    float4 b = *reinterpret_cast<const float4*>(x + i + 4);
    __half2 h[4];
    h[0] = __floats2half2_rn(a.x, a.y);
    h[1] = __floats2half2_rn(a.z, a.w);
    h[2] = __floats2half2_rn(b.x, b.y);
    h[3] = __floats2half2_rn(b.z, b.w);
    *reinterpret_cast<uint4*>(g_X16 + i) = *reinterpret_cast<uint4*>(h);
}

// ---------------- kernel 2: W' = W + alpha * B@A  -> fp16 ---------------------
__global__ void wprep_kernel(const float* __restrict__ W,
                             const float* __restrict__ Aq, const float* __restrict__ Bq,
                             const float* __restrict__ Ak, const float* __restrict__ Bk,
                             const float* __restrict__ Av, const float* __restrict__ Bv,
                             const float* __restrict__ alpha_p) {
    __shared__ float sA[RANK][128];   // A_seg[r][k]
    __shared__ float sB[128][RANK];   // B_seg[d][r]
    int n0 = blockIdx.x * 128;
    int k0 = blockIdx.y * 128;
    int seg = n0 >> 10;
    int nl0 = n0 & 1023;
    const float* A = (seg == 0) ? Aq : (seg == 1) ? Ak : Av;
    const float* B = (seg == 0) ? Bq : (seg == 1) ? Bk : Bv;
    int tid = threadIdx.x;
    for (int i = tid; i < RANK * 128; i += 256)
        sA[i >> 7][i & 127] = A[(size_t)(i >> 7) * DIM + k0 + (i & 127)];
    for (int i = tid; i < 128 * RANK; i += 256)
        sB[i >> 4][i & 15] = B[(size_t)(nl0 + (i >> 4)) * RANK + (i & 15)];
    __syncthreads();
    float al = *alpha_p;
    for (int e = tid; e < 128 * 128; e += 256) {
        int d = e >> 7, c = e & 127;
        float acc = 0.f;
#pragma unroll
        for (int r = 0; r < RANK; r++) acc += sB[d][r] * sA[r][c];
        size_t gi = (size_t)(n0 + d) * DIM + k0 + c;
        g_W16[gi] = __float2half_rn(W[gi] + al * acc);
    }
}

// ---------------- kernel 3: HMMA GEMM (mma.sync) + bias epilogue --------------
// out[M,N] = X16[M,K] @ W16[N,K]^T + bias ;  M=8192 N=3072 K=1024
// CTA tile 128x256, 8 warps in 2x4 grid, warp tile 64x64.
#define BM 128
#define BN 256
#define BK 64
#define KCHUNKS (DIM / BK)                 // 16
#define STAGE_BYTES (BM * 128 + BN * 128)  // 16KB A + 32KB B = 49152
#define NSTAGES 3
#define GEMM_SMEM (NSTAGES * STAGE_BYTES)  // 147456

// smem layout per stage: A rows [BM][128B], B rows [BN][128B];
// 16B-chunk XOR swizzle: chunk' = chunk ^ (row & 7) -> conflict-free ldmatrix.
__device__ __forceinline__ void load_stage(uint32_t sb, int tid,
                                           const char* gA, const char* gB,
                                           int kc, int s) {
    uint32_t sa = sb + s * STAGE_BYTES;
    uint32_t sbb = sa + BM * 128;
    const char* a = gA + kc * (BK * 2);
    const char* b = gB + kc * (BK * 2);
#pragma unroll
    for (int i = 0; i < 4; i++) {          // A: 128 rows x 8 chunks
        int seg = i * 256 + tid;
        int r = seg >> 3, ch = seg & 7;
        CP_ASYNC16(sa + r * 128 + ((ch ^ (r & 7)) << 4),
                   a + (size_t)r * (DIM * 2) + ch * 16);
    }
#pragma unroll
    for (int i = 0; i < 8; i++) {          // B: 256 rows x 8 chunks
        int seg = i * 256 + tid;
        int r = seg >> 3, ch = seg & 7;
        CP_ASYNC16(sbb + r * 128 + ((ch ^ (r & 7)) << 4),
                   b + (size_t)r * (DIM * 2) + ch * 16);
    }
}

__global__ void __launch_bounds__(256, 1)
gemm_kernel(const float* __restrict__ bias, float* __restrict__ out) {
    extern __shared__ char smem[];
    uint32_t sb = smem_u32(smem);
    const int tid = threadIdx.x, wid = tid >> 5, lane = tid & 31;
    const int m0 = blockIdx.y * BM, n0 = blockIdx.x * BN;
    const int wm = wid >> 2;   // 0..1 -> 64 rows each
    const int wn = wid & 3;    // 0..3 -> 64 cols each

    const char* gA = (const char*)(g_X16 + (size_t)m0 * DIM);
    const char* gB = (const char*)(g_W16 + (size_t)n0 * DIM);

    float c[4][8][4];
#pragma unroll
    for (int i = 0; i < 4; i++)
#pragma unroll
        for (int j = 0; j < 8; j++)
#pragma unroll
            for (int k = 0; k < 4; k++) c[i][j][k] = 0.f;

    const int lrow = (lane & 7) + ((lane >> 3) & 1) * 8;  // row within 16-row tile
    const int lch = (lane >> 4);                           // 0/1: 16B chunk half

    load_stage(sb, tid, gA, gB, 0, 0);
    CP_ASYNC_COMMIT();
    load_stage(sb, tid, gA, gB, 1, 1);
    CP_ASYNC_COMMIT();

    for (int kc = 0; kc < KCHUNKS; kc++) {
        if (kc + 2 < KCHUNKS) CP_ASYNC_WAIT(1);
        else                  CP_ASYNC_WAIT(0);
        __syncthreads();

        if (kc + 2 < KCHUNKS) {
            load_stage(sb, tid, gA, gB, kc + 2, (kc + 2) % NSTAGES);
            CP_ASYNC_COMMIT();
        }

        uint32_t sa = sb + (kc % NSTAGES) * STAGE_BYTES;
        uint32_t sbb = sa + BM * 128;

#pragma unroll
        for (int ks = 0; ks < 4; ks++) {       // four k16 steps in BK=64
            uint32_t af[4][4];
#pragma unroll
            for (int mt = 0; mt < 4; mt++) {
                int r = wm * 64 + mt * 16 + lrow;
                int ch = 2 * ks + lch;
                ldmatrix_x4(af[mt], sa + r * 128 + ((ch ^ (r & 7)) << 4));
            }
            uint32_t bf[4][4];
#pragma unroll
            for (int nt = 0; nt < 4; nt++) {
                int r = wn * 64 + nt * 16 + lrow;
                int ch = 2 * ks + lch;
                ldmatrix_x4(bf[nt], sbb + r * 128 + ((ch ^ (r & 7)) << 4));
            }
#pragma unroll
            for (int mt = 0; mt < 4; mt++)
#pragma unroll
                for (int n8 = 0; n8 < 8; n8++) {
                    int nt = n8 >> 1, hi = n8 & 1;
                    mma16816(c[mt][n8], af[mt], bf[nt][hi], bf[nt][2 + hi]);
                }
        }
    }

    // ------- epilogue: +bias, direct float2 stores -------
#pragma unroll
    for (int n8 = 0; n8 < 8; n8++) {
        int n = n0 + wn * 64 + n8 * 8 + ((lane & 3) << 1);
        float bv0 = bias[n], bv1 = bias[n + 1];
#pragma unroll
        for (int mt = 0; mt < 4; mt++) {
            int m = m0 + wm * 64 + mt * 16 + (lane >> 2);
            float2 v0 = make_float2(c[mt][n8][0] + bv0, c[mt][n8][1] + bv1);
            float2 v1 = make_float2(c[mt][n8][2] + bv0, c[mt][n8][3] + bv1);
            *reinterpret_cast<float2*>(out + (size_t)m * N_TOTAL + n) = v0;
            *reinterpret_cast<float2*>(out + (size_t)(m + 8) * N_TOTAL + n) = v1;
        }
    }
}

// ---------------- launch -------------------------------------------------------
extern "C" void kernel_launch(void* const* d_in, const int* in_sizes, int n_in,
                              void* d_out, int out_size) {
    const float* x     = (const float*)d_in[0];
    const float* W_qkv = (const float*)d_in[1];
    const float* b_qkv = (const float*)d_in[2];
    const float* A_q   = (const float*)d_in[3];
    const float* B_q   = (const float*)d_in[4];
    const float* A_k   = (const float*)d_in[5];
    const float* B_k   = (const float*)d_in[6];
    const float* A_v   = (const float*)d_in[7];
    const float* B_v   = (const float*)d_in[8];
    const float* alpha = (const float*)d_in[9];
    float* out = (float*)d_out;

    static bool attr_done = false;
    if (!attr_done) {
        cudaFuncSetAttribute(gemm_kernel, cudaFuncAttributeMaxDynamicSharedMemorySize, GEMM_SMEM);
        attr_done = true;
    }

    convert_x_kernel<<<(M_TOTAL * DIM) / (256 * 8), 256>>>(x);
    wprep_kernel<<<dim3(N_TOTAL / 128, DIM / 128), 256>>>(W_qkv, A_q, B_q, A_k, B_k, A_v, B_v, alpha);
    gemm_kernel<<<dim3(N_TOTAL / BN, M_TOTAL / BM), 256, GEMM_SMEM>>>(b_qkv, out);
}

// round 4
// speedup vs baseline: 1.1851x; 1.1851x over previous
#include <cuda_runtime.h>
#include <cuda_fp16.h>
#include <cstdint>

#define DIM 1024
#define M_TOTAL 8192
#define N_TOTAL 3072
#define RANK 16

// ---------------- scratch (module-static device arrays; no runtime alloc) ----
__device__ __half g_X16[(size_t)M_TOTAL * DIM];   // 16 MB fp16 activations
__device__ __half g_W16[(size_t)N_TOTAL * DIM];   // 6 MB fp16 merged weights

// ---------------- PTX helpers (baseline ISA only: sm_80-era) ------------------
__device__ __forceinline__ uint32_t smem_u32(const void* p) {
    uint32_t a;
    asm("{ .reg .u64 t; cvta.to.shared.u64 t, %1; cvt.u32.u64 %0, t; }" : "=r"(a) : "l"(p));
    return a;
}

#define CP_ASYNC16(dst_smem, src_g) \
    asm volatile("cp.async.cg.shared.global [%0], [%1], 16;" :: "r"(dst_smem), "l"(src_g) : "memory")
#define CP_ASYNC_COMMIT() asm volatile("cp.async.commit_group;" ::: "memory")
#define CP_ASYNC_WAIT(n)  asm volatile("cp.async.wait_group %0;" :: "n"(n) : "memory")

__device__ __forceinline__ void ldmatrix_x4(uint32_t* r, uint32_t addr) {
    asm volatile("ldmatrix.sync.aligned.m8n8.x4.shared.b16 {%0,%1,%2,%3}, [%4];"
                 : "=r"(r[0]), "=r"(r[1]), "=r"(r[2]), "=r"(r[3]) : "r"(addr));
}

__device__ __forceinline__ void mma16816(float* c, const uint32_t* a,
                                         uint32_t b0, uint32_t b1) {
    asm volatile(
        "mma.sync.aligned.m16n8k16.row.col.f32.f16.f16.f32 "
        "{%0,%1,%2,%3}, {%4,%5,%6,%7}, {%8,%9}, {%0,%1,%2,%3};"
        : "+f"(c[0]), "+f"(c[1]), "+f"(c[2]), "+f"(c[3])
        : "r"(a[0]), "r"(a[1]), "r"(a[2]), "r"(a[3]), "r"(b0), "r"(b1));
}

// ---------------- fused prep kernel -------------------------------------------
// Blocks [0, 4096): x fp32 -> fp16 (8 elems/thread, vectorized)
// Blocks [4096, 4288): W' = W + alpha * B@A -> fp16 (128x128 tile each)
#define CONVERT_BLOCKS 4096
#define WPREP_BLOCKS ((N_TOTAL / 128) * (DIM / 128))   // 24 * 8 = 192

__global__ void __launch_bounds__(256)
prep_kernel(const float* __restrict__ x, const float* __restrict__ W,
            const float* __restrict__ Aq, const float* __restrict__ Bq,
            const float* __restrict__ Ak, const float* __restrict__ Bk,
            const float* __restrict__ Av, const float* __restrict__ Bv,
            const float* __restrict__ alpha_p) {
    int tid = threadIdx.x;
    if (blockIdx.x < CONVERT_BLOCKS) {
        size_t i = ((size_t)blockIdx.x * 256 + tid) * 8;
        float4 a = *reinterpret_cast<const float4*>(x + i);
        float4 b = *reinterpret_cast<const float4*>(x + i + 4);
        __half2 h[4];
        h[0] = __floats2half2_rn(a.x, a.y);
        h[1] = __floats2half2_rn(a.z, a.w);
        h[2] = __floats2half2_rn(b.x, b.y);
        h[3] = __floats2half2_rn(b.z, b.w);
        *reinterpret_cast<uint4*>(g_X16 + i) = *reinterpret_cast<uint4*>(h);
        return;
    }
    __shared__ float sA[RANK][128];   // A_seg[r][k]
    __shared__ float sB[128][RANK];   // B_seg[d][r]
    int idx = blockIdx.x - CONVERT_BLOCKS;
    int n0 = (idx % (N_TOTAL / 128)) * 128;
    int k0 = (idx / (N_TOTAL / 128)) * 128;
    int seg = n0 >> 10;
    int nl0 = n0 & 1023;
    const float* A = (seg == 0) ? Aq : (seg == 1) ? Ak : Av;
    const float* B = (seg == 0) ? Bq : (seg == 1) ? Bk : Bv;
    for (int i = tid; i < RANK * 128; i += 256)
        sA[i >> 7][i & 127] = A[(size_t)(i >> 7) * DIM + k0 + (i & 127)];
    for (int i = tid; i < 128 * RANK; i += 256)
        sB[i >> 4][i & 15] = B[(size_t)(nl0 + (i >> 4)) * RANK + (i & 15)];
    __syncthreads();
    float al = *alpha_p;
    for (int e = tid; e < 128 * 128; e += 256) {
        int d = e >> 7, c = e & 127;
        float acc = 0.f;
#pragma unroll
        for (int r = 0; r < RANK; r++) acc += sB[d][r] * sA[r][c];
        size_t gi = (size_t)(n0 + d) * DIM + k0 + c;
        g_W16[gi] = __float2half_rn(W[gi] + al * acc);
    }
}

// ---------------- GEMM: HMMA (mma.sync) + bias epilogue -----------------------
// out[M,N] = X16[M,K] @ W16[N,K]^T + bias ;  M=8192 N=3072 K=1024
// CTA 128x128, 8 warps (2x4), warp tile 64x32, 3-stage cp.async, occupancy 2.
#define BM 128
#define BN 128
#define BK 64
#define KCHUNKS (DIM / BK)                 // 16
#define STAGE_BYTES (BM * 128 + BN * 128)  // 32768
#define NSTAGES 3
#define GEMM_SMEM (NSTAGES * STAGE_BYTES)  // 98304

// 16B-chunk XOR swizzle: chunk' = chunk ^ (row & 7) -> conflict-free ldmatrix.
__device__ __forceinline__ void load_stage(uint32_t sb, int tid,
                                           const char* gA, const char* gB,
                                           int kc, int s) {
    uint32_t sa = sb + s * STAGE_BYTES;
    uint32_t sbb = sa + BM * 128;
    const char* a = gA + kc * (BK * 2);
    const char* b = gB + kc * (BK * 2);
#pragma unroll
    for (int i = 0; i < 4; i++) {          // 128 rows x 8 chunks, 256 threads
        int seg = i * 256 + tid;
        int r = seg >> 3, ch = seg & 7;
        CP_ASYNC16(sa + r * 128 + ((ch ^ (r & 7)) << 4),
                   a + (size_t)r * (DIM * 2) + ch * 16);
    }
#pragma unroll
    for (int i = 0; i < 4; i++) {
        int seg = i * 256 + tid;
        int r = seg >> 3, ch = seg & 7;
        CP_ASYNC16(sbb + r * 128 + ((ch ^ (r & 7)) << 4),
                   b + (size_t)r * (DIM * 2) + ch * 16);
    }
}

__global__ void __launch_bounds__(256, 2)
gemm_kernel(const float* __restrict__ bias, float* __restrict__ out) {
    extern __shared__ char smem[];
    uint32_t sb = smem_u32(smem);
    const int tid = threadIdx.x, wid = tid >> 5, lane = tid & 31;
    const int m0 = blockIdx.y * BM, n0 = blockIdx.x * BN;
    const int wm = wid >> 2;   // 0..1 -> 64 rows each
    const int wn = wid & 3;    // 0..3 -> 32 cols each

    const char* gA = (const char*)(g_X16 + (size_t)m0 * DIM);
    const char* gB = (const char*)(g_W16 + (size_t)n0 * DIM);

    float c[4][4][4];
#pragma unroll
    for (int i = 0; i < 4; i++)
#pragma unroll
        for (int j = 0; j < 4; j++)
#pragma unroll
            for (int k = 0; k < 4; k++) c[i][j][k] = 0.f;

    const int lrow = (lane & 7) + ((lane >> 3) & 1) * 8;  // row within 16-row tile
    const int lch = (lane >> 4);                           // 0/1: 16B chunk half

    load_stage(sb, tid, gA, gB, 0, 0);
    CP_ASYNC_COMMIT();
    load_stage(sb, tid, gA, gB, 1, 1);
    CP_ASYNC_COMMIT();

    for (int kc = 0; kc < KCHUNKS; kc++) {
        if (kc + 2 < KCHUNKS) CP_ASYNC_WAIT(1);
        else                  CP_ASYNC_WAIT(0);
        __syncthreads();

        if (kc + 2 < KCHUNKS) {
            load_stage(sb, tid, gA, gB, kc + 2, (kc + 2) % NSTAGES);
            CP_ASYNC_COMMIT();
        }

        uint32_t sa = sb + (kc % NSTAGES) * STAGE_BYTES;
        uint32_t sbb = sa + BM * 128;

#pragma unroll
        for (int ks = 0; ks < 4; ks++) {       // four k16 steps in BK=64
            uint32_t af[4][4];
#pragma unroll
            for (int mt = 0; mt < 4; mt++) {
                int r = wm * 64 + mt * 16 + lrow;
                int ch = 2 * ks + lch;
                ldmatrix_x4(af[mt], sa + r * 128 + ((ch ^ (r & 7)) << 4));
            }
            uint32_t bf[2][4];
#pragma unroll
            for (int nt = 0; nt < 2; nt++) {
                int r = wn * 32 + nt * 16 + lrow;
                int ch = 2 * ks + lch;
                ldmatrix_x4(bf[nt], sbb + r * 128 + ((ch ^ (r & 7)) << 4));
            }
#pragma unroll
            for (int mt = 0; mt < 4; mt++)
#pragma unroll
                for (int n8 = 0; n8 < 4; n8++) {
                    int nt = n8 >> 1, hi = n8 & 1;
                    mma16816(c[mt][n8], af[mt], bf[nt][hi], bf[nt][2 + hi]);
                }
        }
    }

    // ------- epilogue: +bias, direct float2 stores -------
#pragma unroll
    for (int n8 = 0; n8 < 4; n8++) {
        int n = n0 + wn * 32 + n8 * 8 + ((lane & 3) << 1);
        float bv0 = bias[n], bv1 = bias[n + 1];
#pragma unroll
        for (int mt = 0; mt < 4; mt++) {
            int m = m0 + wm * 64 + mt * 16 + (lane >> 2);
            float2 v0 = make_float2(c[mt][n8][0] + bv0, c[mt][n8][1] + bv1);
            float2 v1 = make_float2(c[mt][n8][2] + bv0, c[mt][n8][3] + bv1);
            *reinterpret_cast<float2*>(out + (size_t)m * N_TOTAL + n) = v0;
            *reinterpret_cast<float2*>(out + (size_t)(m + 8) * N_TOTAL + n) = v1;
        }
    }
}

// ---------------- launch -------------------------------------------------------
extern "C" void kernel_launch(void* const* d_in, const int* in_sizes, int n_in,
                              void* d_out, int out_size) {
    const float* x     = (const float*)d_in[0];
    const float* W_qkv = (const float*)d_in[1];
    const float* b_qkv = (const float*)d_in[2];
    const float* A_q   = (const float*)d_in[3];
    const float* B_q   = (const float*)d_in[4];
    const float* A_k   = (const float*)d_in[5];
    const float* B_k   = (const float*)d_in[6];
    const float* A_v   = (const float*)d_in[7];
    const float* B_v   = (const float*)d_in[8];
    const float* alpha = (const float*)d_in[9];
    float* out = (float*)d_out;

    static bool attr_done = false;
    if (!attr_done) {
        cudaFuncSetAttribute(gemm_kernel, cudaFuncAttributeMaxDynamicSharedMemorySize, GEMM_SMEM);
        attr_done = true;
    }

    prep_kernel<<<CONVERT_BLOCKS + WPREP_BLOCKS, 256>>>(
        x, W_qkv, A_q, B_q, A_k, B_k, A_v, B_v, alpha);
    gemm_kernel<<<dim3(N_TOTAL / BN, M_TOTAL / BM), 256, GEMM_SMEM>>>(b_qkv, out);
}

// round 5
// speedup vs baseline: 1.2241x; 1.0329x over previous
#include <cuda_runtime.h>
#include <cuda_fp16.h>
#include <cstdint>

#define DIM 1024
#define M_TOTAL 8192
#define N_TOTAL 3072
#define RANK 16

// ---------------- scratch (module-static device arrays; no runtime alloc) ----
__device__ __half g_X16[(size_t)M_TOTAL * DIM];   // 16 MB fp16 activations
__device__ __half g_W16[(size_t)N_TOTAL * DIM];   // 6 MB fp16 merged weights

// ---------------- PTX helpers (baseline ISA only: sm_80-era) ------------------
__device__ __forceinline__ uint32_t smem_u32(const void* p) {
    uint32_t a;
    asm("{ .reg .u64 t; cvta.to.shared.u64 t, %1; cvt.u32.u64 %0, t; }" : "=r"(a) : "l"(p));
    return a;
}

#define CP_ASYNC16(dst_smem, src_g) \
    asm volatile("cp.async.cg.shared.global [%0], [%1], 16;" :: "r"(dst_smem), "l"(src_g) : "memory")
#define CP_ASYNC_COMMIT() asm volatile("cp.async.commit_group;" ::: "memory")
#define CP_ASYNC_WAIT(n)  asm volatile("cp.async.wait_group %0;" :: "n"(n) : "memory")

__device__ __forceinline__ void ldmatrix_x4(uint32_t* r, uint32_t addr) {
    asm volatile("ldmatrix.sync.aligned.m8n8.x4.shared.b16 {%0,%1,%2,%3}, [%4];"
                 : "=r"(r[0]), "=r"(r[1]), "=r"(r[2]), "=r"(r[3]) : "r"(addr));
}

__device__ __forceinline__ void mma16816(float* c, const uint32_t* a,
                                         uint32_t b0, uint32_t b1) {
    asm volatile(
        "mma.sync.aligned.m16n8k16.row.col.f32.f16.f16.f32 "
        "{%0,%1,%2,%3}, {%4,%5,%6,%7}, {%8,%9}, {%0,%1,%2,%3};"
        : "+f"(c[0]), "+f"(c[1]), "+f"(c[2]), "+f"(c[3])
        : "r"(a[0]), "r"(a[1]), "r"(a[2]), "r"(a[3]), "r"(b0), "r"(b1));
}

// ---------------- fused prep kernel -------------------------------------------
// Blocks [0, 192): W' = W + alpha * B@A -> fp16 (128x128 tile each; launched
//                  FIRST so the longer-latency work has no serial tail)
// Blocks [192, 192+4096): x fp32 -> fp16 (8 elems/thread, vectorized)
#define WPREP_BLOCKS ((N_TOTAL / 128) * (DIM / 128))   // 24 * 8 = 192
#define CONVERT_BLOCKS 4096

__global__ void __launch_bounds__(256)
prep_kernel(const float* __restrict__ x, const float* __restrict__ W,
            const float* __restrict__ Aq, const float* __restrict__ Bq,
            const float* __restrict__ Ak, const float* __restrict__ Bk,
            const float* __restrict__ Av, const float* __restrict__ Bv,
            const float* __restrict__ alpha_p) {
    int tid = threadIdx.x;
    if (blockIdx.x >= WPREP_BLOCKS) {
        size_t i = ((size_t)(blockIdx.x - WPREP_BLOCKS) * 256 + tid) * 8;
        float4 a = *reinterpret_cast<const float4*>(x + i);
        float4 b = *reinterpret_cast<const float4*>(x + i + 4);
        __half2 h[4];
        h[0] = __floats2half2_rn(a.x, a.y);
        h[1] = __floats2half2_rn(a.z, a.w);
        h[2] = __floats2half2_rn(b.x, b.y);
        h[3] = __floats2half2_rn(b.z, b.w);
        *reinterpret_cast<uint4*>(g_X16 + i) = *reinterpret_cast<uint4*>(h);
        return;
    }
    __shared__ float sA[RANK][128];   // A_seg[r][k]
    __shared__ float sB[128][RANK];   // B_seg[d][r]
    int idx = blockIdx.x;
    int n0 = (idx % (N_TOTAL / 128)) * 128;
    int k0 = (idx / (N_TOTAL / 128)) * 128;
    int seg = n0 >> 10;
    int nl0 = n0 & 1023;
    const float* A = (seg == 0) ? Aq : (seg == 1) ? Ak : Av;
    const float* B = (seg == 0) ? Bq : (seg == 1) ? Bk : Bv;
    for (int i = tid; i < RANK * 128; i += 256)
        sA[i >> 7][i & 127] = A[(size_t)(i >> 7) * DIM + k0 + (i & 127)];
    for (int i = tid; i < 128 * RANK; i += 256)
        sB[i >> 4][i & 15] = B[(size_t)(nl0 + (i >> 4)) * RANK + (i & 15)];
    __syncthreads();
    float al = *alpha_p;
    for (int e = tid; e < 128 * 128; e += 256) {
        int d = e >> 7, c = e & 127;
        float acc = 0.f;
#pragma unroll
        for (int r = 0; r < RANK; r++) acc += sB[d][r] * sA[r][c];
        size_t gi = (size_t)(n0 + d) * DIM + k0 + c;
        g_W16[gi] = __float2half_rn(W[gi] + al * acc);
    }
}

// ---------------- GEMM: HMMA (mma.sync) + bias epilogue -----------------------
// out[M,N] = X16[M,K] @ W16[N,K]^T + bias ;  M=8192 N=3072 K=1024
// CTA 128x128, 8 warps (2x4), warp tile 64x32, 3-stage cp.async, occupancy 2.
// Per-warp ks-phase stagger desynchronizes LDSM (smem port) and HMMA (tensor
// pipe) phases across warps so both pipes run concurrently.
#define BM 128
#define BN 128
#define BK 64
#define KCHUNKS (DIM / BK)                 // 16
#define STAGE_BYTES (BM * 128 + BN * 128)  // 32768
#define NSTAGES 3
#define GEMM_SMEM (NSTAGES * STAGE_BYTES)  // 98304

// 16B-chunk XOR swizzle: chunk' = chunk ^ (row & 7) -> conflict-free ldmatrix.
__device__ __forceinline__ void load_stage(uint32_t sb, int tid,
                                           const char* gA, const char* gB,
                                           int kc, int s) {
    uint32_t sa = sb + s * STAGE_BYTES;
    uint32_t sbb = sa + BM * 128;
    const char* a = gA + kc * (BK * 2);
    const char* b = gB + kc * (BK * 2);
#pragma unroll
    for (int i = 0; i < 4; i++) {          // 128 rows x 8 chunks, 256 threads
        int seg = i * 256 + tid;
        int r = seg >> 3, ch = seg & 7;
        CP_ASYNC16(sa + r * 128 + ((ch ^ (r & 7)) << 4),
                   a + (size_t)r * (DIM * 2) + ch * 16);
    }
#pragma unroll
    for (int i = 0; i < 4; i++) {
        int seg = i * 256 + tid;
        int r = seg >> 3, ch = seg & 7;
        CP_ASYNC16(sbb + r * 128 + ((ch ^ (r & 7)) << 4),
                   b + (size_t)r * (DIM * 2) + ch * 16);
    }
}

__global__ void __launch_bounds__(256, 2)
gemm_kernel(const float* __restrict__ bias, float* __restrict__ out) {
    extern __shared__ char smem[];
    uint32_t sb = smem_u32(smem);
    const int tid = threadIdx.x, wid = tid >> 5, lane = tid & 31;
    const int m0 = blockIdx.y * BM, n0 = blockIdx.x * BN;
    const int wm = wid >> 2;   // 0..1 -> 64 rows each
    const int wn = wid & 3;    // 0..3 -> 32 cols each

    const char* gA = (const char*)(g_X16 + (size_t)m0 * DIM);
    const char* gB = (const char*)(g_W16 + (size_t)n0 * DIM);

    float c[4][4][4];
#pragma unroll
    for (int i = 0; i < 4; i++)
#pragma unroll
        for (int j = 0; j < 4; j++)
#pragma unroll
            for (int k = 0; k < 4; k++) c[i][j][k] = 0.f;

    const int lrow = (lane & 7) + ((lane >> 3) & 1) * 8;  // row within 16-row tile
    const int lch = (lane >> 4);                           // 0/1: 16B chunk half

    load_stage(sb, tid, gA, gB, 0, 0);
    CP_ASYNC_COMMIT();
    load_stage(sb, tid, gA, gB, 1, 1);
    CP_ASYNC_COMMIT();

    for (int kc = 0; kc < KCHUNKS; kc++) {
        if (kc + 2 < KCHUNKS) CP_ASYNC_WAIT(1);
        else                  CP_ASYNC_WAIT(0);
        __syncthreads();

        if (kc + 2 < KCHUNKS) {
            load_stage(sb, tid, gA, gB, kc + 2, (kc + 2) % NSTAGES);
            CP_ASYNC_COMMIT();
        }

        uint32_t sa = sb + (kc % NSTAGES) * STAGE_BYTES;
        uint32_t sbb = sa + BM * 128;

#pragma unroll
        for (int ks = 0; ks < 4; ks++) {
            // per-warp phase stagger: ks iterations commute (independent
            // partial sums), so each warp starts at a different phase.
            int ksp = (ks + wid) & 3;
            int ch = 2 * ksp + lch;
            uint32_t bf[2][4];
#pragma unroll
            for (int nt = 0; nt < 2; nt++) {
                int r = wn * 32 + nt * 16 + lrow;
                ldmatrix_x4(bf[nt], sbb + r * 128 + ((ch ^ (r & 7)) << 4));
            }
            uint32_t af[4][4];
#pragma unroll
            for (int mt = 0; mt < 4; mt++) {
                int r = wm * 64 + mt * 16 + lrow;
                ldmatrix_x4(af[mt], sa + r * 128 + ((ch ^ (r & 7)) << 4));
            }
#pragma unroll
            for (int mt = 0; mt < 4; mt++)
#pragma unroll
                for (int n8 = 0; n8 < 4; n8++) {
                    int nt = n8 >> 1, hi = n8 & 1;
                    mma16816(c[mt][n8], af[mt], bf[nt][hi], bf[nt][2 + hi]);
                }
        }
    }

    // ------- epilogue: +bias, direct float2 stores -------
#pragma unroll
    for (int n8 = 0; n8 < 4; n8++) {
        int n = n0 + wn * 32 + n8 * 8 + ((lane & 3) << 1);
        float bv0 = bias[n], bv1 = bias[n + 1];
#pragma unroll
        for (int mt = 0; mt < 4; mt++) {
            int m = m0 + wm * 64 + mt * 16 + (lane >> 2);
            float2 v0 = make_float2(c[mt][n8][0] + bv0, c[mt][n8][1] + bv1);
            float2 v1 = make_float2(c[mt][n8][2] + bv0, c[mt][n8][3] + bv1);
            *reinterpret_cast<float2*>(out + (size_t)m * N_TOTAL + n) = v0;
            *reinterpret_cast<float2*>(out + (size_t)(m + 8) * N_TOTAL + n) = v1;
        }
    }
}

// ---------------- launch -------------------------------------------------------
extern "C" void kernel_launch(void* const* d_in, const int* in_sizes, int n_in,
                              void* d_out, int out_size) {
    const float* x     = (const float*)d_in[0];
    const float* W_qkv = (const float*)d_in[1];
    const float* b_qkv = (const float*)d_in[2];
    const float* A_q   = (const float*)d_in[3];
    const float* B_q   = (const float*)d_in[4];
    const float* A_k   = (const float*)d_in[5];
    const float* B_k   = (const float*)d_in[6];
    const float* A_v   = (const float*)d_in[7];
    const float* B_v   = (const float*)d_in[8];
    const float* alpha = (const float*)d_in[9];
    float* out = (float*)d_out;

    static bool attr_done = false;
    if (!attr_done) {
        cudaFuncSetAttribute(gemm_kernel, cudaFuncAttributeMaxDynamicSharedMemorySize, GEMM_SMEM);
        attr_done = true;
    }

    prep_kernel<<<WPREP_BLOCKS + CONVERT_BLOCKS, 256>>>(
        x, W_qkv, A_q, B_q, A_k, B_k, A_v, B_v, alpha);
    gemm_kernel<<<dim3(N_TOTAL / BN, M_TOTAL / BM), 256, GEMM_SMEM>>>(b_qkv, out);
}

// round 6
// speedup vs baseline: 1.2363x; 1.0100x over previous
#include <cuda_runtime.h>
#include <cuda_fp16.h>
#include <cstdint>

#define DIM 1024
#define M_TOTAL 8192
#define N_TOTAL 3072
#define RANK 16

// ---------------- scratch (module-static device arrays; no runtime alloc) ----
__device__ __half g_X16[(size_t)M_TOTAL * DIM];   // 16 MB fp16 activations
__device__ __half g_W16[(size_t)N_TOTAL * DIM];   // 6 MB fp16 merged weights

// ---------------- PTX helpers (baseline ISA only: sm_80-era) ------------------
__device__ __forceinline__ uint32_t smem_u32(const void* p) {
    uint32_t a;
    asm("{ .reg .u64 t; cvta.to.shared.u64 t, %1; cvt.u32.u64 %0, t; }" : "=r"(a) : "l"(p));
    return a;
}

#define CP_ASYNC16(dst_smem, src_g) \
    asm volatile("cp.async.cg.shared.global [%0], [%1], 16;" :: "r"(dst_smem), "l"(src_g) : "memory")
#define CP_ASYNC_COMMIT() asm volatile("cp.async.commit_group;" ::: "memory")
#define CP_ASYNC_WAIT(n)  asm volatile("cp.async.wait_group %0;" :: "n"(n) : "memory")

__device__ __forceinline__ void ldmatrix_x4(uint32_t* r, uint32_t addr) {
    asm volatile("ldmatrix.sync.aligned.m8n8.x4.shared.b16 {%0,%1,%2,%3}, [%4];"
                 : "=r"(r[0]), "=r"(r[1]), "=r"(r[2]), "=r"(r[3]) : "r"(addr));
}

__device__ __forceinline__ void mma16816(float* c, const uint32_t* a,
                                         uint32_t b0, uint32_t b1) {
    asm volatile(
        "mma.sync.aligned.m16n8k16.row.col.f32.f16.f16.f32 "
        "{%0,%1,%2,%3}, {%4,%5,%6,%7}, {%8,%9}, {%0,%1,%2,%3};"
        : "+f"(c[0]), "+f"(c[1]), "+f"(c[2]), "+f"(c[3])
        : "r"(a[0]), "r"(a[1]), "r"(a[2]), "r"(a[3]), "r"(b0), "r"(b1));
}

// ---------------- fused prep kernel -------------------------------------------
// Blocks [0, 192): W' = W + alpha * B@A -> fp16 (128x128 tile each, first)
// Blocks [192, 192+4096): x fp32 -> fp16 (8 elems/thread, vectorized)
#define WPREP_BLOCKS ((N_TOTAL / 128) * (DIM / 128))   // 192
#define CONVERT_BLOCKS 4096

__global__ void __launch_bounds__(256)
prep_kernel(const float* __restrict__ x, const float* __restrict__ W,
            const float* __restrict__ Aq, const float* __restrict__ Bq,
            const float* __restrict__ Ak, const float* __restrict__ Bk,
            const float* __restrict__ Av, const float* __restrict__ Bv,
            const float* __restrict__ alpha_p) {
    int tid = threadIdx.x;
    if (blockIdx.x >= WPREP_BLOCKS) {
        size_t i = ((size_t)(blockIdx.x - WPREP_BLOCKS) * 256 + tid) * 8;
        float4 a = *reinterpret_cast<const float4*>(x + i);
        float4 b = *reinterpret_cast<const float4*>(x + i + 4);
        __half2 h[4];
        h[0] = __floats2half2_rn(a.x, a.y);
        h[1] = __floats2half2_rn(a.z, a.w);
        h[2] = __floats2half2_rn(b.x, b.y);
        h[3] = __floats2half2_rn(b.z, b.w);
        *reinterpret_cast<uint4*>(g_X16 + i) = *reinterpret_cast<uint4*>(h);
        return;
    }
    __shared__ float sA[RANK][128];   // A_seg[r][k]
    __shared__ float sB[128][RANK];   // B_seg[d][r]
    int idx = blockIdx.x;
    int n0 = (idx % (N_TOTAL / 128)) * 128;
    int k0 = (idx / (N_TOTAL / 128)) * 128;
    int seg = n0 >> 10;
    int nl0 = n0 & 1023;
    const float* A = (seg == 0) ? Aq : (seg == 1) ? Ak : Av;
    const float* B = (seg == 0) ? Bq : (seg == 1) ? Bk : Bv;
    for (int i = tid; i < RANK * 128; i += 256)
        sA[i >> 7][i & 127] = A[(size_t)(i >> 7) * DIM + k0 + (i & 127)];
    for (int i = tid; i < 128 * RANK; i += 256)
        sB[i >> 4][i & 15] = B[(size_t)(nl0 + (i >> 4)) * RANK + (i & 15)];
    __syncthreads();
    float al = *alpha_p;
    for (int e = tid; e < 128 * 128; e += 256) {
        int d = e >> 7, c = e & 127;
        float acc = 0.f;
#pragma unroll
        for (int r = 0; r < RANK; r++) acc += sB[d][r] * sA[r][c];
        size_t gi = (size_t)(n0 + d) * DIM + k0 + c;
        g_W16[gi] = __float2half_rn(W[gi] + al * acc);
    }
}

// ---------------- GEMM: HMMA (mma.sync) + bias epilogue -----------------------
// out[M,N] = X16[M,K] @ W16[N,K]^T + bias ;  M=8192 N=3072 K=1024
// CTA tile 128x128 with 128 threads (2x2 warps), warp tile 64x64.
// Occupancy 2 -> two independent CTAs per SM hide each other's sync bubbles,
// while the 64x64 warp tile cuts smem fragment traffic per FLOP by 1.5x.
#define BM 128
#define BN 128
#define BK 64
#define KCHUNKS (DIM / BK)                 // 16
#define STAGE_BYTES (BM * 128 + BN * 128)  // 32768
#define NSTAGES 3
#define GEMM_SMEM (NSTAGES * STAGE_BYTES)  // 98304

// 16B-chunk XOR swizzle: chunk' = chunk ^ (row & 7) -> conflict-free ldmatrix.
__device__ __forceinline__ void load_stage(uint32_t sb, int tid,
                                           const char* gA, const char* gB,
                                           int kc, int s) {
    uint32_t sa = sb + s * STAGE_BYTES;
    uint32_t sbb = sa + BM * 128;
    const char* a = gA + kc * (BK * 2);
    const char* b = gB + kc * (BK * 2);
#pragma unroll
    for (int i = 0; i < 8; i++) {          // 128 rows x 8 chunks, 128 threads
        int seg = i * 128 + tid;
        int r = seg >> 3, ch = seg & 7;
        CP_ASYNC16(sa + r * 128 + ((ch ^ (r & 7)) << 4),
                   a + (size_t)r * (DIM * 2) + ch * 16);
    }
#pragma unroll
    for (int i = 0; i < 8; i++) {
        int seg = i * 128 + tid;
        int r = seg >> 3, ch = seg & 7;
        CP_ASYNC16(sbb + r * 128 + ((ch ^ (r & 7)) << 4),
                   b + (size_t)r * (DIM * 2) + ch * 16);
    }
}

__global__ void __launch_bounds__(128, 2)
gemm_kernel(const float* __restrict__ bias, float* __restrict__ out) {
    extern __shared__ char smem[];
    uint32_t sb = smem_u32(smem);
    const int tid = threadIdx.x, wid = tid >> 5, lane = tid & 31;
    const int m0 = blockIdx.y * BM, n0 = blockIdx.x * BN;
    const int wm = wid >> 1;   // 0..1 -> 64 rows each
    const int wn = wid & 1;    // 0..1 -> 64 cols each

    const char* gA = (const char*)(g_X16 + (size_t)m0 * DIM);
    const char* gB = (const char*)(g_W16 + (size_t)n0 * DIM);

    float c[4][8][4];
#pragma unroll
    for (int i = 0; i < 4; i++)
#pragma unroll
        for (int j = 0; j < 8; j++)
#pragma unroll
            for (int k = 0; k < 4; k++) c[i][j][k] = 0.f;

    const int lrow = (lane & 7) + ((lane >> 3) & 1) * 8;  // row within 16-row tile
    const int lch = (lane >> 4);                           // 0/1: 16B chunk half

    load_stage(sb, tid, gA, gB, 0, 0);
    CP_ASYNC_COMMIT();
    load_stage(sb, tid, gA, gB, 1, 1);
    CP_ASYNC_COMMIT();

    for (int kc = 0; kc < KCHUNKS; kc++) {
        if (kc + 2 < KCHUNKS) CP_ASYNC_WAIT(1);
        else                  CP_ASYNC_WAIT(0);
        __syncthreads();

        if (kc + 2 < KCHUNKS) {
            load_stage(sb, tid, gA, gB, kc + 2, (kc + 2) % NSTAGES);
            CP_ASYNC_COMMIT();
        }

        uint32_t sa = sb + (kc % NSTAGES) * STAGE_BYTES;
        uint32_t sbb = sa + BM * 128;

#pragma unroll
        for (int ks = 0; ks < 4; ks++) {
            int ch = 2 * ks + lch;
            uint32_t af[4][4];
#pragma unroll
            for (int mt = 0; mt < 4; mt++) {
                int r = wm * 64 + mt * 16 + lrow;
                ldmatrix_x4(af[mt], sa + r * 128 + ((ch ^ (r & 7)) << 4));
            }
            uint32_t bf[4][4];
#pragma unroll
            for (int nt = 0; nt < 4; nt++) {
                int r = wn * 64 + nt * 16 + lrow;
                ldmatrix_x4(bf[nt], sbb + r * 128 + ((ch ^ (r & 7)) << 4));
            }
#pragma unroll
            for (int mt = 0; mt < 4; mt++)
#pragma unroll
                for (int n8 = 0; n8 < 8; n8++) {
                    int nt = n8 >> 1, hi = n8 & 1;
                    mma16816(c[mt][n8], af[mt], bf[nt][hi], bf[nt][2 + hi]);
                }
        }
    }

    // ------- epilogue: +bias, direct float2 stores -------
#pragma unroll
    for (int n8 = 0; n8 < 8; n8++) {
        int n = n0 + wn * 64 + n8 * 8 + ((lane & 3) << 1);
        float bv0 = bias[n], bv1 = bias[n + 1];
#pragma unroll
        for (int mt = 0; mt < 4; mt++) {
            int m = m0 + wm * 64 + mt * 16 + (lane >> 2);
            float2 v0 = make_float2(c[mt][n8][0] + bv0, c[mt][n8][1] + bv1);
            float2 v1 = make_float2(c[mt][n8][2] + bv0, c[mt][n8][3] + bv1);
            *reinterpret_cast<float2*>(out + (size_t)m * N_TOTAL + n) = v0;
            *reinterpret_cast<float2*>(out + (size_t)(m + 8) * N_TOTAL + n) = v1;
        }
    }
}

// ---------------- launch -------------------------------------------------------
extern "C" void kernel_launch(void* const* d_in, const int* in_sizes, int n_in,
                              void* d_out, int out_size) {
    const float* x     = (const float*)d_in[0];
    const float* W_qkv = (const float*)d_in[1];
    const float* b_qkv = (const float*)d_in[2];
    const float* A_q   = (const float*)d_in[3];
    const float* B_q   = (const float*)d_in[4];
    const float* A_k   = (const float*)d_in[5];
    const float* B_k   = (const float*)d_in[6];
    const float* A_v   = (const float*)d_in[7];
    const float* B_v   = (const float*)d_in[8];
    const float* alpha = (const float*)d_in[9];
    float* out = (float*)d_out;

    static bool attr_done = false;
    if (!attr_done) {
        cudaFuncSetAttribute(gemm_kernel, cudaFuncAttributeMaxDynamicSharedMemorySize, GEMM_SMEM);
        attr_done = true;
    }

    prep_kernel<<<WPREP_BLOCKS + CONVERT_BLOCKS, 256>>>(
        x, W_qkv, A_q, B_q, A_k, B_k, A_v, B_v, alpha);
    gemm_kernel<<<dim3(N_TOTAL / BN, M_TOTAL / BM), 128, GEMM_SMEM>>>(b_qkv, out);
}